// round 1
// baseline (speedup 1.0000x reference)
#include <cuda_runtime.h>
#include <cuda_bf16.h>
#include <math.h>

#define NN 4096
#define C 7
#define MAXDEG 512
#define SIG1 0.731058578630004896f   // sigmoid(1)

// ---- static device scratch (no allocations allowed) ----
__device__ int    g_deg[NN];
__device__ int    g_diag[NN];
__device__ int    g_nbr[NN * MAXDEG];
__device__ double g_dcc[C * C];      // correction sums per (label_p, label_q)
__device__ int    g_hi[C * C];       // has_inter flags
__device__ int    g_zc[NN * C];      // per (p, class j): #masked label-j q in sparse set with sub==0

__device__ __forceinline__ float vfun(float sub, float inter) {
    // v = 1 - sigmoid(r) = 1/(1+exp(r)),  r = (1 + s*sub)/(1 + s*inter)
    float r = (1.0f + SIG1 * sub) / (1.0f + SIG1 * inter);
    return 1.0f / (1.0f + expf(r));
}

// ---- zero accumulators (fresh every launch; graph-replay safe) ----
__global__ void k_init() {
    int idx = blockIdx.x * blockDim.x + threadIdx.x;
    int stride = gridDim.x * blockDim.x;
    for (int i = idx; i < NN * C; i += stride) g_zc[i] = 0;
    for (int i = idx; i < C * C; i += stride) { g_dcc[i] = 0.0; g_hi[i] = 0; }
}

// ---- build degree + neighbor lists + diagonal flags (one 64MB coalesced pass) ----
__global__ void k_build(const int* __restrict__ adj) {
    int p = blockIdx.x;
    __shared__ int cnt;
    __shared__ int diag;
    if (threadIdx.x == 0) { cnt = 0; diag = 0; }
    __syncthreads();
    const int* row = adj + (size_t)p * NN;
    for (int q = threadIdx.x; q < NN; q += blockDim.x) {
        if (row[q]) {
            int s = atomicAdd(&cnt, 1);
            if (s < MAXDEG) g_nbr[p * MAXDEG + s] = q;
            if (q == p) diag = 1;
        }
    }
    __syncthreads();
    if (threadIdx.x == 0) {
        g_deg[p]  = (cnt < MAXDEG) ? cnt : MAXDEG;
        g_diag[p] = diag;
    }
}

// ---- wedge kernel: sparse inter/sub corrections + exact gating info ----
__global__ void k_wedge(const float* __restrict__ preds,
                        const int* __restrict__ labels,
                        const int* __restrict__ mask) {
    __shared__ unsigned int cnt[NN];      // low 20 bits: inter count; bit 20: is-neighbor mark
    __shared__ float sdcc[C];
    __shared__ int   shi[C], szc[C];
    __shared__ float s_end, s_v0;

    int p = blockIdx.x;
    if (!mask[p]) return;                 // all pair-term contributions require mask[p]
    int degp = g_deg[p];
    if (degp == 0) return;                // no neighbors -> no sparse pairs, sub==0 everywhere

    for (int i = threadIdx.x; i < NN; i += blockDim.x) cnt[i] = 0u;
    if (threadIdx.x < C) { sdcc[threadIdx.x] = 0.0f; shi[threadIdx.x] = 0; szc[threadIdx.x] = 0; }
    int lp = labels[p];
    if (threadIdx.x == 0) {
        s_end = expf(-preds[p * C + lp]);         // exp(-gamma*diagP[p]), gamma=1
        s_v0  = vfun((float)degp, 0.0f);
    }
    __syncthreads();

    const int* np = g_nbr + p * MAXDEG;
    int wid = threadIdx.x >> 5, lane = threadIdx.x & 31;
    int nwarp = blockDim.x >> 5;
    for (int a = wid; a < degp; a += nwarp) {
        int k = np[a];
        int dk = g_deg[k];
        const int* nk = g_nbr + k * MAXDEG;
        for (int b = lane; b < dk; b += 32) atomicAdd(&cnt[nk[b]], 1u);
    }
    for (int a = threadIdx.x; a < degp; a += blockDim.x)
        atomicAdd(&cnt[np[a]], 1u << 20);
    __syncthreads();

    float endp = s_end, v0 = s_v0;
    for (int q = threadIdx.x; q < NN; q += blockDim.x) {
        unsigned int c = cnt[q];
        if (!c) continue;
        int inter = (int)(c & 0xFFFFFu);
        int corr  = ((c >> 20) && !g_diag[q]) ? 1 : 0;
        if (inter == 0 && corr == 0) continue;   // behaves exactly like the default pair
        if (!mask[q]) continue;                  // all remaining uses need mask[q]
        int lq = labels[q];
        int sub = degp - inter - corr;
        if (inter > 0) shi[lq] = 1;
        if (sub == 0)  atomicAdd(&szc[lq], 1);
        if (lq != lp) {
            float d = endp * expf(preds[q * C + lp]) *
                      (vfun((float)sub, (float)inter) - v0);
            atomicAdd(&sdcc[lq], d);
        }
    }
    __syncthreads();
    if (threadIdx.x < C) {
        int j = threadIdx.x;
        if (sdcc[j] != 0.0f) atomicAdd(&g_dcc[lp * C + j], (double)sdcc[j]);
        if (shi[j]) g_hi[lp * C + j] = 1;
        if (szc[j]) g_zc[p * C + j] = szc[j];    // p unique per block: plain store
    }
}

// ---- finalize: ce + factorized base sum + gated totals ----
__global__ void k_final(const float* __restrict__ preds,
                        const int* __restrict__ labels,
                        const int* __restrict__ mask,
                        float* __restrict__ out) {
    __shared__ int    sN[C];
    __shared__ float  sT[C * C];
    __shared__ float  sU[C];
    __shared__ int    shs[C * C];
    __shared__ double sce;
    int tid = threadIdx.x;
    if (tid < C)     { sN[tid] = 0; sU[tid] = 0.0f; }
    if (tid < C * C) { sT[tid] = 0.0f; shs[tid] = 0; }
    if (tid == 0) sce = 0.0;
    __syncthreads();

    for (int p = tid; p < NN; p += blockDim.x)
        if (mask[p]) atomicAdd(&sN[labels[p]], 1);
    __syncthreads();

    double ce_local = 0.0;
    for (int p = tid; p < NN; p += blockDim.x) {
        const float* r = preds + p * C;
        int lp = labels[p];
        float mx = r[0];
        #pragma unroll
        for (int i = 1; i < C; i++) mx = fmaxf(mx, r[i]);
        float se = 0.0f;
        #pragma unroll
        for (int i = 0; i < C; i++) se += expf(r[i] - mx);
        float lse = mx + logf(se);
        ce_local += (double)(r[lp] - lse);
        if (mask[p]) {
            #pragma unroll
            for (int i = 0; i < C; i++) atomicAdd(&sT[i * C + lp], expf(r[i]));
            int dp = g_deg[p];
            atomicAdd(&sU[lp], expf(-r[lp]) * vfun((float)dp, 0.0f));
            if (dp > 0) {
                #pragma unroll
                for (int j = 0; j < C; j++)
                    if (g_zc[p * C + j] < sN[j]) shs[lp * C + j] = 1;
            }
        }
    }
    atomicAdd(&sce, ce_local);
    __syncthreads();

    if (tid == 0) {
        double tot = 0.0;
        for (int i = 0; i < C; i++) {
            double inv_i = (sN[i] > 0) ? 1.0 / (double)sN[i] : 0.0;
            for (int j = 0; j < C; j++) {
                if (i == j) continue;
                if (!(shs[i * C + j] && g_hi[i * C + j])) continue;
                double inv_j = (sN[j] > 0) ? 1.0 / (double)sN[j] : 0.0;
                tot += inv_i * inv_j *
                       ((double)sU[i] * (double)sT[i * C + j] + g_dcc[i * C + j]);
            }
        }
        double ce = -(sce / (double)NN);
        out[0] = (float)(ce + 0.001 * tot);
    }
}

extern "C" void kernel_launch(void* const* d_in, const int* in_sizes, int n_in,
                              void* d_out, int out_size) {
    const float* preds  = (const float*)d_in[0];
    const int*   labels = (const int*)d_in[1];
    const int*   mask   = (const int*)d_in[2];
    const int*   adj    = (const int*)d_in[3];
    float* out = (float*)d_out;

    k_init <<<64, 256>>>();
    k_build<<<NN, 256>>>(adj);
    k_wedge<<<NN, 256>>>(preds, labels, mask);
    k_final<<<1, 256>>>(preds, labels, mask, out);
}

// round 2
// speedup vs baseline: 1.6004x; 1.6004x over previous
#include <cuda_runtime.h>
#include <cuda_bf16.h>
#include <math.h>

#define NN 4096
#define C 7
#define MAXDEG 512
#define SIG1 0.731058578630004896f   // sigmoid(1)

// ---- static device scratch (no allocations allowed) ----
__device__ int    g_deg[NN];
__device__ int    g_diag[NN];
__device__ int    g_nbr[NN * MAXDEG];
__device__ double g_dcc[C * C];      // correction sums per (label_p, label_q)
__device__ int    g_hi[C * C];       // has_inter flags (from sparse pairs)
__device__ int    g_zc[NN * C];      // per (p, class j): #masked label-j q in sparse set with sub==0
__device__ int    g_N[C];            // per-class masked counts
__device__ float  g_T[C * C];        // T[i,j] = sum_{q masked, l=j} exp(preds[q,i])
__device__ float  g_U[C];            // U[i]   = sum_{p masked, l=i} exp(-diagP_p) * v0(p)
__device__ int    g_hs[C * C];       // has_sub flags
__device__ double g_ce;              // sum of (logit - lse)

__device__ __forceinline__ float vfun(float sub, float inter) {
    // v = 1 - sigmoid(r) = 1/(1+exp(r)),  r = (1 + s*sub)/(1 + s*inter)
    float r = (1.0f + SIG1 * sub) / (1.0f + SIG1 * inter);
    return 1.0f / (1.0f + expf(r));
}

// ---- zero accumulators + per-class masked counts (graph-replay safe) ----
__global__ void k_init(const int* __restrict__ labels, const int* __restrict__ mask) {
    int idx = blockIdx.x * blockDim.x + threadIdx.x;
    int stride = gridDim.x * blockDim.x;
    for (int i = idx; i < NN * C; i += stride) g_zc[i] = 0;
    for (int i = idx; i < C * C; i += stride) {
        g_dcc[i] = 0.0; g_hi[i] = 0; g_T[i] = 0.0f; g_hs[i] = 0;
    }
    for (int i = idx; i < C; i += stride) { g_N[i] = 0; g_U[i] = 0.0f; }
    if (idx == 0) g_ce = 0.0;
    for (int p = idx; p < NN; p += stride)
        if (mask[p]) atomicAdd(&g_N[labels[p]], 1);
}

// ---- build degree + neighbor lists + diagonal flags (one 64MB coalesced pass) ----
__global__ void k_build(const int* __restrict__ adj) {
    int p = blockIdx.x;
    __shared__ int cnt;
    __shared__ int diag;
    if (threadIdx.x == 0) { cnt = 0; diag = 0; }
    __syncthreads();
    const int4* row = (const int4*)(adj + (size_t)p * NN);
    for (int qb = threadIdx.x; qb < NN / 4; qb += blockDim.x) {
        int4 v = row[qb];
        int q = qb * 4;
        if (v.x) { int s = atomicAdd(&cnt, 1); if (s < MAXDEG) g_nbr[p * MAXDEG + s] = q;     if (q     == p) diag = 1; }
        if (v.y) { int s = atomicAdd(&cnt, 1); if (s < MAXDEG) g_nbr[p * MAXDEG + s] = q + 1; if (q + 1 == p) diag = 1; }
        if (v.z) { int s = atomicAdd(&cnt, 1); if (s < MAXDEG) g_nbr[p * MAXDEG + s] = q + 2; if (q + 2 == p) diag = 1; }
        if (v.w) { int s = atomicAdd(&cnt, 1); if (s < MAXDEG) g_nbr[p * MAXDEG + s] = q + 3; if (q + 3 == p) diag = 1; }
    }
    __syncthreads();
    if (threadIdx.x == 0) {
        g_deg[p]  = (cnt < MAXDEG) ? cnt : MAXDEG;
        g_diag[p] = diag;
    }
}

// ---- wedge kernel: sparse inter/sub corrections + exact gating info ----
__global__ void k_wedge(const float* __restrict__ preds,
                        const int* __restrict__ labels,
                        const int* __restrict__ mask) {
    __shared__ unsigned int cnt[NN];      // low 20 bits: inter count; bit 20: is-neighbor mark
    __shared__ float sdcc[C];
    __shared__ int   shi[C], szc[C];
    __shared__ float s_end, s_v0;

    int p = blockIdx.x;
    if (!mask[p]) return;                 // all pair-term contributions require mask[p]
    int degp = g_deg[p];
    if (degp == 0) return;                // no neighbors -> no sparse pairs, sub==0 everywhere

    for (int i = threadIdx.x; i < NN; i += blockDim.x) cnt[i] = 0u;
    if (threadIdx.x < C) { sdcc[threadIdx.x] = 0.0f; shi[threadIdx.x] = 0; szc[threadIdx.x] = 0; }
    int lp = labels[p];
    if (threadIdx.x == 0) {
        s_end = expf(-preds[p * C + lp]);         // exp(-gamma*diagP[p]), gamma=1
        s_v0  = vfun((float)degp, 0.0f);
    }
    __syncthreads();

    const int* np = g_nbr + p * MAXDEG;
    int wid = threadIdx.x >> 5, lane = threadIdx.x & 31;
    int nwarp = blockDim.x >> 5;
    for (int a = wid; a < degp; a += nwarp) {
        int k = np[a];
        int dk = g_deg[k];
        const int* nk = g_nbr + k * MAXDEG;
        for (int b = lane; b < dk; b += 32) atomicAdd(&cnt[nk[b]], 1u);
    }
    for (int a = threadIdx.x; a < degp; a += blockDim.x)
        atomicAdd(&cnt[np[a]], 1u << 20);
    __syncthreads();

    float endp = s_end, v0 = s_v0;
    for (int q = threadIdx.x; q < NN; q += blockDim.x) {
        unsigned int c = cnt[q];
        if (!c) continue;
        int inter = (int)(c & 0xFFFFFu);
        int corr  = ((c >> 20) && !g_diag[q]) ? 1 : 0;
        if (inter == 0 && corr == 0) continue;   // behaves exactly like the default pair
        if (!mask[q]) continue;                  // all remaining uses need mask[q]
        int lq = labels[q];
        int sub = degp - inter - corr;
        if (inter > 0) shi[lq] = 1;
        if (sub == 0)  atomicAdd(&szc[lq], 1);
        if (lq != lp) {
            float d = endp * expf(preds[q * C + lp]) *
                      (vfun((float)sub, (float)inter) - v0);
            atomicAdd(&sdcc[lq], d);
        }
    }
    __syncthreads();
    if (threadIdx.x < C) {
        int j = threadIdx.x;
        if (sdcc[j] != 0.0f) atomicAdd(&g_dcc[lp * C + j], (double)sdcc[j]);
        if (shi[j]) g_hi[lp * C + j] = 1;
        if (szc[j]) g_zc[p * C + j] = szc[j];    // p unique per block: plain store
    }
}

// ---- grid-wide per-node stats: ce + T + U + has_sub ----
__global__ void k_stats(const float* __restrict__ preds,
                        const int* __restrict__ labels,
                        const int* __restrict__ mask) {
    __shared__ float sT[C * C];
    __shared__ float sU[C];
    __shared__ int   shs[C * C];
    __shared__ float sce;
    int tid = threadIdx.x;
    if (tid < C * C) { sT[tid] = 0.0f; shs[tid] = 0; }
    if (tid < C) sU[tid] = 0.0f;
    if (tid == 0) sce = 0.0f;
    __syncthreads();

    float ce_local = 0.0f;
    for (int p = blockIdx.x * blockDim.x + tid; p < NN; p += gridDim.x * blockDim.x) {
        const float* r = preds + p * C;
        int lp = labels[p];
        float v0 = r[0], v1 = r[1], v2 = r[2], v3 = r[3], v4 = r[4], v5 = r[5], v6 = r[6];
        float mx = fmaxf(fmaxf(fmaxf(v0, v1), fmaxf(v2, v3)), fmaxf(fmaxf(v4, v5), v6));
        float e0 = expf(v0 - mx), e1 = expf(v1 - mx), e2 = expf(v2 - mx), e3 = expf(v3 - mx);
        float e4 = expf(v4 - mx), e5 = expf(v5 - mx), e6 = expf(v6 - mx);
        float se = e0 + e1 + e2 + e3 + e4 + e5 + e6;
        float lse = mx + logf(se);
        ce_local += r[lp] - lse;
        if (mask[p]) {
            float emx = expf(mx);   // exp(r[i]) = e_i * exp(mx)
            atomicAdd(&sT[0 * C + lp], e0 * emx);
            atomicAdd(&sT[1 * C + lp], e1 * emx);
            atomicAdd(&sT[2 * C + lp], e2 * emx);
            atomicAdd(&sT[3 * C + lp], e3 * emx);
            atomicAdd(&sT[4 * C + lp], e4 * emx);
            atomicAdd(&sT[5 * C + lp], e5 * emx);
            atomicAdd(&sT[6 * C + lp], e6 * emx);
            int dp = g_deg[p];
            atomicAdd(&sU[lp], expf(-r[lp]) * vfun((float)dp, 0.0f));
            if (dp > 0) {
                #pragma unroll
                for (int j = 0; j < C; j++)
                    if (g_zc[p * C + j] < g_N[j]) shs[lp * C + j] = 1;
            }
        }
    }
    atomicAdd(&sce, ce_local);
    __syncthreads();
    if (tid < C * C) {
        if (sT[tid] != 0.0f) atomicAdd(&g_T[tid], sT[tid]);
        if (shs[tid]) g_hs[tid] = 1;
    }
    if (tid < C && sU[tid] != 0.0f) atomicAdd(&g_U[tid], sU[tid]);
    if (tid == 0) atomicAdd(&g_ce, (double)sce);
}

// ---- tiny combine over 49 class pairs ----
__global__ void k_combine(float* __restrict__ out) {
    double tot = 0.0;
    for (int i = 0; i < C; i++) {
        double inv_i = (g_N[i] > 0) ? 1.0 / (double)g_N[i] : 0.0;
        for (int j = 0; j < C; j++) {
            if (i == j) continue;
            if (!(g_hs[i * C + j] && g_hi[i * C + j])) continue;
            double inv_j = (g_N[j] > 0) ? 1.0 / (double)g_N[j] : 0.0;
            tot += inv_i * inv_j *
                   ((double)g_U[i] * (double)g_T[i * C + j] + g_dcc[i * C + j]);
        }
    }
    double ce = -(g_ce / (double)NN);
    out[0] = (float)(ce + 0.001 * tot);
}

extern "C" void kernel_launch(void* const* d_in, const int* in_sizes, int n_in,
                              void* d_out, int out_size) {
    const float* preds  = (const float*)d_in[0];
    const int*   labels = (const int*)d_in[1];
    const int*   mask   = (const int*)d_in[2];
    const int*   adj    = (const int*)d_in[3];
    float* out = (float*)d_out;

    k_init   <<<64, 256>>>(labels, mask);
    k_build  <<<NN, 256>>>(adj);
    k_wedge  <<<NN, 256>>>(preds, labels, mask);
    k_stats  <<<32, 128>>>(preds, labels, mask);
    k_combine<<<1, 1>>>(out);
}

// round 3
// speedup vs baseline: 2.2192x; 1.3866x over previous
#include <cuda_runtime.h>
#include <cuda_bf16.h>
#include <math.h>

#define NN 4096
#define C 7
#define MAXDEG 96
#define LISTCAP 2048
#define SIG1 0.731058578630004896f   // sigmoid(1)

// ---- static device scratch (no allocations allowed) ----
__device__ int    g_deg[NN];
__device__ int    g_diag[NN];
__device__ int    g_nbr[NN * MAXDEG];
__device__ double g_dcc[C * C];      // correction sums per (label_p, label_q)
__device__ int    g_hi[C * C];       // has_inter flags
__device__ int    g_hs[C * C];       // has_sub flags
__device__ int    g_N[C];            // per-class masked counts
__device__ float  g_T[C * C];        // T[i,j] = sum_{q masked,l=j} exp(preds[q,i])
__device__ float  g_U[C];            // U[i]   = sum_{p masked,l=i} exp(-diagP_p)*v0(p)
__device__ double g_ce;              // sum of (logit - lse)
__device__ unsigned int g_ticket;    // self-resetting via atomicInc wrap (starts 0)

__device__ __forceinline__ float vfun(float sub, float inter) {
    // v = 1 - sigmoid(r) = 1/(1+exp(r)),  r = (1 + s*sub)/(1 + s*inter)
    float r = (1.0f + SIG1 * sub) / (1.0f + SIG1 * inter);
    return 1.0f / (1.0f + expf(r));
}

// ---- build: neighbor lists + degrees + diag; block 0 also zeroes accums + g_N ----
__global__ void k_build(const int* __restrict__ adj,
                        const int* __restrict__ labels,
                        const int* __restrict__ mask) {
    int p = blockIdx.x;
    int t = threadIdx.x;
    __shared__ int cnt, diag;
    __shared__ int sN[C];

    if (p == 0) {
        // zero accumulators (only block 0 touches these; wedge kernel runs later)
        if (t < C * C) { g_dcc[t] = 0.0; g_hi[t] = 0; g_hs[t] = 0; g_T[t] = 0.0f; }
        if (t < C)     { g_U[t] = 0.0f; sN[t] = 0; }
        if (t == 0)    g_ce = 0.0;
        __syncthreads();
        // per-class masked counts, register-local then smem atomics
        int c0=0,c1=0,c2=0,c3=0,c4=0,c5=0,c6=0;
        for (int i = t; i < NN; i += blockDim.x) {
            if (mask[i]) {
                int l = labels[i];
                c0 += (l==0); c1 += (l==1); c2 += (l==2); c3 += (l==3);
                c4 += (l==4); c5 += (l==5); c6 += (l==6);
            }
        }
        if (c0) atomicAdd(&sN[0], c0);
        if (c1) atomicAdd(&sN[1], c1);
        if (c2) atomicAdd(&sN[2], c2);
        if (c3) atomicAdd(&sN[3], c3);
        if (c4) atomicAdd(&sN[4], c4);
        if (c5) atomicAdd(&sN[5], c5);
        if (c6) atomicAdd(&sN[6], c6);
        __syncthreads();
        if (t < C) g_N[t] = sN[t];
    }

    if (t == 0) { cnt = 0; diag = 0; }
    __syncthreads();
    const int4* row = (const int4*)(adj + (size_t)p * NN);
    for (int qb = t; qb < NN / 4; qb += blockDim.x) {
        int4 v = row[qb];
        int q = qb * 4;
        if (v.x) { int s = atomicAdd(&cnt, 1); if (s < MAXDEG) g_nbr[p * MAXDEG + s] = q;     if (q     == p) diag = 1; }
        if (v.y) { int s = atomicAdd(&cnt, 1); if (s < MAXDEG) g_nbr[p * MAXDEG + s] = q + 1; if (q + 1 == p) diag = 1; }
        if (v.z) { int s = atomicAdd(&cnt, 1); if (s < MAXDEG) g_nbr[p * MAXDEG + s] = q + 2; if (q + 2 == p) diag = 1; }
        if (v.w) { int s = atomicAdd(&cnt, 1); if (s < MAXDEG) g_nbr[p * MAXDEG + s] = q + 3; if (q + 3 == p) diag = 1; }
    }
    __syncthreads();
    if (t == 0) {
        g_deg[p]  = (cnt < MAXDEG) ? cnt : MAXDEG;
        g_diag[p] = diag;
    }
}

// ---- wedge + per-node stats + final combine (last block via ticket) ----
__global__ void k_wedge(const float* __restrict__ preds,
                        const int* __restrict__ labels,
                        const int* __restrict__ mask,
                        float* __restrict__ out) {
    __shared__ unsigned int cnt[NN];     // low 20 bits: inter; bit 20: neighbor mark
    __shared__ int   lst[LISTCAP];
    __shared__ int   nlist;
    __shared__ float sdcc[C];
    __shared__ int   shi[C], szc[C];
    __shared__ float s_end, s_v0;

    int p = blockIdx.x, t = threadIdx.x;
    int mp   = mask[p];
    int degp = g_deg[p];
    int lp   = labels[p];

    // per-node stats: ce (all nodes), T & U (masked). Global REDG, ~49 hot addrs.
    if (t == 0) {
        const float* r = preds + p * C;
        float v0 = r[0], v1 = r[1], v2 = r[2], v3 = r[3], v4 = r[4], v5 = r[5], v6 = r[6];
        float rl = r[lp];
        float mx = fmaxf(fmaxf(fmaxf(v0, v1), fmaxf(v2, v3)), fmaxf(fmaxf(v4, v5), v6));
        float se = expf(v0 - mx) + expf(v1 - mx) + expf(v2 - mx) + expf(v3 - mx)
                 + expf(v4 - mx) + expf(v5 - mx) + expf(v6 - mx);
        atomicAdd(&g_ce, (double)(rl - (mx + logf(se))));
        float endp = expf(-rl);
        float u0 = vfun((float)degp, 0.0f);
        if (mp) {
            atomicAdd(&g_T[0 * C + lp], expf(v0));
            atomicAdd(&g_T[1 * C + lp], expf(v1));
            atomicAdd(&g_T[2 * C + lp], expf(v2));
            atomicAdd(&g_T[3 * C + lp], expf(v3));
            atomicAdd(&g_T[4 * C + lp], expf(v4));
            atomicAdd(&g_T[5 * C + lp], expf(v5));
            atomicAdd(&g_T[6 * C + lp], expf(v6));
            atomicAdd(&g_U[lp], endp * u0);
        }
        s_end = endp;
        s_v0  = u0;
    }

    if (mp && degp > 0) {
        // zero counters + small state
        uint4* c4 = (uint4*)cnt;
        for (int i = t; i < NN / 4; i += blockDim.x) c4[i] = make_uint4(0u, 0u, 0u, 0u);
        if (t < C) { sdcc[t] = 0.0f; shi[t] = 0; szc[t] = 0; }
        if (t == 0) nlist = 0;
        __syncthreads();

        const int* np = g_nbr + p * MAXDEG;
        int wid = t >> 5, lane = t & 31, nw = blockDim.x >> 5;
        for (int a = wid; a < degp; a += nw) {
            int k = np[a];
            int dk = g_deg[k];
            const int* nk = g_nbr + k * MAXDEG;
            for (int b = lane; b < dk; b += 32) {
                int q = nk[b];
                unsigned old = atomicAdd(&cnt[q], 1u);
                if (old == 0u) { int s = atomicAdd(&nlist, 1); if (s < LISTCAP) lst[s] = q; }
            }
        }
        for (int a = t; a < degp; a += blockDim.x) {
            int q = np[a];
            unsigned old = atomicAdd(&cnt[q], 1u << 20);
            if (old == 0u) { int s = atomicAdd(&nlist, 1); if (s < LISTCAP) lst[s] = q; }
        }
        __syncthreads();

        float endp = s_end, v0 = s_v0;
        int nl = nlist;
        if (nl <= LISTCAP) {
            for (int ii = t; ii < nl; ii += blockDim.x) {
                int q = lst[ii];
                unsigned c = cnt[q];
                int inter = (int)(c & 0xFFFFFu);
                int corr  = ((c >> 20) && !g_diag[q]) ? 1 : 0;
                if ((inter | corr) && mask[q]) {
                    int lq = labels[q];
                    int sub = degp - inter - corr;
                    if (inter > 0) shi[lq] = 1;
                    if (sub == 0)  atomicAdd(&szc[lq], 1);
                    if (lq != lp) {
                        float d = endp * expf(preds[q * C + lp]) *
                                  (vfun((float)sub, (float)inter) - v0);
                        atomicAdd(&sdcc[lq], d);
                    }
                }
            }
        } else {                     // overflow fallback: full scan
            for (int q = t; q < NN; q += blockDim.x) {
                unsigned c = cnt[q];
                if (!c) continue;
                int inter = (int)(c & 0xFFFFFu);
                int corr  = ((c >> 20) && !g_diag[q]) ? 1 : 0;
                if ((inter | corr) && mask[q]) {
                    int lq = labels[q];
                    int sub = degp - inter - corr;
                    if (inter > 0) shi[lq] = 1;
                    if (sub == 0)  atomicAdd(&szc[lq], 1);
                    if (lq != lp) {
                        float d = endp * expf(preds[q * C + lp]) *
                                  (vfun((float)sub, (float)inter) - v0);
                        atomicAdd(&sdcc[lq], d);
                    }
                }
            }
        }
        __syncthreads();
        if (t < C) {
            if (sdcc[t] != 0.0f) atomicAdd(&g_dcc[lp * C + t], (double)sdcc[t]);
            if (shi[t]) g_hi[lp * C + t] = 1;
            // has_sub: some masked label-t q with sub>0 (all sub==0 q are in sparse set)
            if (szc[t] < g_N[t]) g_hs[lp * C + t] = 1;
        }
    }

    // ---- ticket: last of NN blocks combines (wraps to 0 -> graph-replay safe) ----
    __threadfence();
    if (t == 0) {
        unsigned tk = atomicInc(&g_ticket, NN - 1);
        if (tk == NN - 1) {
            double tot = 0.0;
            for (int i = 0; i < C; i++) {
                double inv_i = (g_N[i] > 0) ? 1.0 / (double)g_N[i] : 0.0;
                for (int j = 0; j < C; j++) {
                    if (i == j) continue;
                    if (!(g_hs[i * C + j] && g_hi[i * C + j])) continue;
                    double inv_j = (g_N[j] > 0) ? 1.0 / (double)g_N[j] : 0.0;
                    tot += inv_i * inv_j *
                           ((double)g_U[i] * (double)g_T[i * C + j] + g_dcc[i * C + j]);
                }
            }
            out[0] = (float)(-(g_ce / (double)NN) + 0.001 * tot);
        }
    }
}

extern "C" void kernel_launch(void* const* d_in, const int* in_sizes, int n_in,
                              void* d_out, int out_size) {
    const float* preds  = (const float*)d_in[0];
    const int*   labels = (const int*)d_in[1];
    const int*   mask   = (const int*)d_in[2];
    const int*   adj    = (const int*)d_in[3];
    float* out = (float*)d_out;

    k_build<<<NN, 256>>>(adj, labels, mask);
    k_wedge<<<NN, 256>>>(preds, labels, mask, out);
}

// round 5
// speedup vs baseline: 2.2971x; 1.0351x over previous
#include <cuda_runtime.h>
#include <cuda_bf16.h>
#include <math.h>

#define NN 4096
#define C 7
#define MAXDEG 96
#define LISTCAP 2048
#define SIG1 0.731058578630004896f   // sigmoid(1)

// ---- static device scratch (zero-initialized at module load; self-cleaning) ----
__device__ int    g_deg[NN];
__device__ int    g_diag[NN];
__device__ float  g_endp[NN];        // exp(-preds[p, l_p])
__device__ int    g_nbr[NN * MAXDEG];
__device__ double g_dcc[C * C];      // correction sums per (label_p, label_q)
__device__ int    g_hi[C * C];       // has_inter flags
__device__ int    g_hs[C * C];       // has_sub flags
__device__ int    g_N[C];            // per-class masked counts (overwritten each call)
__device__ float  g_T[C * C];        // T[i,j] = sum_{q masked,l=j} exp(preds[q,i])
__device__ float  g_U[C];            // U[i]   = sum_{p masked,l=i} exp(-diagP_p)*v0(p)
__device__ double g_ce;              // sum of (logit - lse)
__device__ unsigned int g_ticket;    // wraps via atomicInc -> replay safe

__device__ __forceinline__ float vfun(float sub, float inter) {
    float r = (1.0f + SIG1 * sub) / (1.0f + SIG1 * inter);
    return 1.0f / (1.0f + expf(r));
}

// ---- build: neighbor lists + degree + diag + per-node stats; block 0 computes g_N ----
__global__ void k_build(const int* __restrict__ adj,
                        const float* __restrict__ preds,
                        const int* __restrict__ labels,
                        const int* __restrict__ mask) {
    int p = blockIdx.x, t = threadIdx.x;
    __shared__ int cnt, diag;
    __shared__ int sN[C];

    if (p == 0) {
        if (t < C) sN[t] = 0;
        __syncthreads();
        int c0=0,c1=0,c2=0,c3=0,c4=0,c5=0,c6=0;
        for (int i = t; i < NN; i += blockDim.x) {
            if (mask[i]) {
                int l = labels[i];
                c0 += (l==0); c1 += (l==1); c2 += (l==2); c3 += (l==3);
                c4 += (l==4); c5 += (l==5); c6 += (l==6);
            }
        }
        if (c0) atomicAdd(&sN[0], c0);
        if (c1) atomicAdd(&sN[1], c1);
        if (c2) atomicAdd(&sN[2], c2);
        if (c3) atomicAdd(&sN[3], c3);
        if (c4) atomicAdd(&sN[4], c4);
        if (c5) atomicAdd(&sN[5], c5);
        if (c6) atomicAdd(&sN[6], c6);
        __syncthreads();
        if (t < C) g_N[t] = sN[t];
    }

    if (t == 0) { cnt = 0; diag = 0; }
    __syncthreads();
    const int4* row = (const int4*)(adj + (size_t)p * NN);
    for (int qb = t; qb < NN / 4; qb += blockDim.x) {
        int4 v = row[qb];
        int q = qb * 4;
        if (v.x) { int s = atomicAdd(&cnt, 1); if (s < MAXDEG) g_nbr[p * MAXDEG + s] = q;     if (q     == p) diag = 1; }
        if (v.y) { int s = atomicAdd(&cnt, 1); if (s < MAXDEG) g_nbr[p * MAXDEG + s] = q + 1; if (q + 1 == p) diag = 1; }
        if (v.z) { int s = atomicAdd(&cnt, 1); if (s < MAXDEG) g_nbr[p * MAXDEG + s] = q + 2; if (q + 2 == p) diag = 1; }
        if (v.w) { int s = atomicAdd(&cnt, 1); if (s < MAXDEG) g_nbr[p * MAXDEG + s] = q + 3; if (q + 3 == p) diag = 1; }
    }
    __syncthreads();
    if (t == 0) {
        int degp = (cnt < MAXDEG) ? cnt : MAXDEG;
        g_deg[p]  = degp;
        g_diag[p] = diag;
        // per-node stats (accumulators were reset by previous call's combine)
        const float* r = preds + p * C;
        int lp = labels[p];
        float v0 = r[0], v1 = r[1], v2 = r[2], v3 = r[3], v4 = r[4], v5 = r[5], v6 = r[6];
        float rl = r[lp];
        float mx = fmaxf(fmaxf(fmaxf(v0, v1), fmaxf(v2, v3)), fmaxf(fmaxf(v4, v5), v6));
        float se = expf(v0 - mx) + expf(v1 - mx) + expf(v2 - mx) + expf(v3 - mx)
                 + expf(v4 - mx) + expf(v5 - mx) + expf(v6 - mx);
        atomicAdd(&g_ce, (double)(rl - (mx + logf(se))));
        float endp = expf(-rl);
        g_endp[p] = endp;
        if (mask[p]) {
            atomicAdd(&g_T[0 * C + lp], expf(v0));
            atomicAdd(&g_T[1 * C + lp], expf(v1));
            atomicAdd(&g_T[2 * C + lp], expf(v2));
            atomicAdd(&g_T[3 * C + lp], expf(v3));
            atomicAdd(&g_T[4 * C + lp], expf(v4));
            atomicAdd(&g_T[5 * C + lp], expf(v5));
            atomicAdd(&g_T[6 * C + lp], expf(v6));
            atomicAdd(&g_U[lp], endp * vfun((float)degp, 0.0f));
        }
    }
}

// ---- wedge: packed 16-bit counters, touched list, combine by last ticket ----
__global__ void __launch_bounds__(128, 16)
k_wedge(const float* __restrict__ preds,
        const int* __restrict__ labels,
        const int* __restrict__ mask,
        float* __restrict__ out) {
    __shared__ unsigned int  cnt[NN / 2];     // two 16-bit lanes: bits0-14 inter, bit15 nbr mark
    __shared__ unsigned short lst[LISTCAP];
    __shared__ int   nlist;
    __shared__ float sdcc[C];
    __shared__ int   shi[C], szc[C];

    int p = blockIdx.x, t = threadIdx.x;
    int mp   = mask[p];
    int degp = g_deg[p];
    int lp   = labels[p];

    if (mp && degp > 0) {
        uint4* c4 = (uint4*)cnt;
        for (int i = t; i < NN / 8; i += blockDim.x) c4[i] = make_uint4(0u, 0u, 0u, 0u);
        if (t < C) { sdcc[t] = 0.0f; shi[t] = 0; szc[t] = 0; }
        if (t == 0) nlist = 0;
        __syncthreads();

        const int* np = g_nbr + p * MAXDEG;
        int wid = t >> 5, lane = t & 31, nw = blockDim.x >> 5;
        for (int a = wid; a < degp; a += nw) {
            int k = np[a];
            int dk = g_deg[k];
            const int* nk = g_nbr + k * MAXDEG;
            for (int b = lane; b < dk; b += 32) {
                int q = nk[b];
                int sh = (q & 1) * 16;
                unsigned old = atomicAdd(&cnt[q >> 1], 1u << sh);
                if (((old >> sh) & 0xFFFFu) == 0u) {
                    int s = atomicAdd(&nlist, 1);
                    if (s < LISTCAP) lst[s] = (unsigned short)q;
                }
            }
        }
        for (int a = t; a < degp; a += blockDim.x) {
            int q = np[a];
            int sh = (q & 1) * 16;
            unsigned old = atomicOr(&cnt[q >> 1], 0x8000u << sh);
            if (((old >> sh) & 0xFFFFu) == 0u) {
                int s = atomicAdd(&nlist, 1);
                if (s < LISTCAP) lst[s] = (unsigned short)q;
            }
        }
        __syncthreads();

        float endp = g_endp[p];
        float v0   = vfun((float)degp, 0.0f);
        int nl = nlist;
        if (nl <= LISTCAP) {
            for (int ii = t; ii < nl; ii += blockDim.x) {
                int q = lst[ii];
                unsigned c = (cnt[q >> 1] >> ((q & 1) * 16)) & 0xFFFFu;
                int inter = (int)(c & 0x7FFFu);
                int corr  = ((c >> 15) && !g_diag[q]) ? 1 : 0;
                if ((inter | corr) && mask[q]) {
                    int lq = labels[q];
                    int sub = degp - inter - corr;
                    if (inter > 0) shi[lq] = 1;
                    if (sub == 0)  atomicAdd(&szc[lq], 1);
                    if (lq != lp) {
                        float d = endp * expf(preds[q * C + lp]) *
                                  (vfun((float)sub, (float)inter) - v0);
                        atomicAdd(&sdcc[lq], d);
                    }
                }
            }
        } else {                     // overflow fallback: full scan over packed words
            for (int w = t; w < NN / 2; w += blockDim.x) {
                unsigned word = cnt[w];
                if (!word) continue;
                #pragma unroll
                for (int h = 0; h < 2; h++) {
                    unsigned c = (word >> (h * 16)) & 0xFFFFu;
                    if (!c) continue;
                    int q = w * 2 + h;
                    int inter = (int)(c & 0x7FFFu);
                    int corr  = ((c >> 15) && !g_diag[q]) ? 1 : 0;
                    if ((inter | corr) && mask[q]) {
                        int lq = labels[q];
                        int sub = degp - inter - corr;
                        if (inter > 0) shi[lq] = 1;
                        if (sub == 0)  atomicAdd(&szc[lq], 1);
                        if (lq != lp) {
                            float d = endp * expf(preds[q * C + lp]) *
                                      (vfun((float)sub, (float)inter) - v0);
                            atomicAdd(&sdcc[lq], d);
                        }
                    }
                }
            }
        }
        __syncthreads();
        if (t < C) {
            if (sdcc[t] != 0.0f) atomicAdd(&g_dcc[lp * C + t], (double)sdcc[t]);
            if (shi[t]) g_hi[lp * C + t] = 1;
            if (szc[t] < g_N[t]) g_hs[lp * C + t] = 1;   // exists masked label-t q with sub>0
        }
    }

    // ---- last block combines, then resets accumulators for next replay ----
    __threadfence();
    if (t == 0) {
        unsigned tk = atomicInc(&g_ticket, NN - 1);
        if (tk == NN - 1) {
            double tot = 0.0;
            for (int i = 0; i < C; i++) {
                double inv_i = (g_N[i] > 0) ? 1.0 / (double)g_N[i] : 0.0;
                for (int j = 0; j < C; j++) {
                    if (i == j) continue;
                    if (g_hs[i * C + j] && g_hi[i * C + j]) {
                        double inv_j = (g_N[j] > 0) ? 1.0 / (double)g_N[j] : 0.0;
                        tot += inv_i * inv_j *
                               ((double)g_U[i] * (double)g_T[i * C + j] + g_dcc[i * C + j]);
                    }
                }
            }
            out[0] = (float)(-(g_ce / (double)NN) + 0.001 * tot);
            // reset accumulators for the next graph replay
            for (int i = 0; i < C * C; i++) {
                g_dcc[i] = 0.0; g_hi[i] = 0; g_hs[i] = 0; g_T[i] = 0.0f;
            }
            for (int i = 0; i < C; i++) g_U[i] = 0.0f;
            g_ce = 0.0;
        }
    }
}

extern "C" void kernel_launch(void* const* d_in, const int* in_sizes, int n_in,
                              void* d_out, int out_size) {
    const float* preds  = (const float*)d_in[0];
    const int*   labels = (const int*)d_in[1];
    const int*   mask   = (const int*)d_in[2];
    const int*   adj    = (const int*)d_in[3];
    float* out = (float*)d_out;

    k_build<<<NN, 256>>>(adj, preds, labels, mask);
    k_wedge<<<NN, 128>>>(preds, labels, mask, out);
}